// round 13
// baseline (speedup 1.0000x reference)
#include <cuda_runtime.h>
#include <cuda_fp16.h>
#include <cstdint>

// B=2, H=16, S=2048, D=64 fp32 attention; out = [context | weights].
// prep_k/prep_v: K -> fp16 (natural), V -> fp16 transposed [d][s].
// k1 (scores):  mask (cp.async staged) -> fp16 mma scores -> exp -> W16 + row sums.
// k2 (context): streams W16 tiles; uses them as mma A-frags (context) AND
//               normalizes them to fp32 weights. V fp16 from L2.

#define SDIM    2048
#define DDIM    64
#define BHN     32
#define TQ      128
#define WQ      16
#define CK      64
#define NCH     32
#define KSTRH   88      // halfs; bank = (12*grp+tig) mod 32, bijective
#define MSTRI   68      // mask smem row stride (ints)
#define WSTRH   72      // W16 smem stride (halfs): bank 4*grp+tig, bijective
#define VSTRH2  72      // V smem stride in k2
#define THREADS 256
#define SCALE   0.125f

// k1 smem: K 2*64*88*2 = 22528 | M 2*128*68*4 = 69632  -> 92160 B
#define SMEM1_BYTES (22528 + 69632)
// k2 smem: W 2*128*72*2 = 36864 | V 2*64*72*2 = 18432 | sri 512 -> 55808 B
#define SMEM2_BYTES (36864 + 18432 + 512)

__device__ float  g_ri[BHN * SDIM];
__device__ __half g_Kh [(size_t)BHN * SDIM * DDIM];
__device__ __half g_Vt [(size_t)BHN * DDIM * SDIM];
__device__ __half g_W16[(size_t)BHN * SDIM * SDIM];   // 268 MB scratch

__device__ __forceinline__ uint32_t f22h(float x, float y) {
    __half2 h = __floats2half2_rn(x, y);
    return *(uint32_t*)&h;
}

__device__ __forceinline__ void mma_f16(float c[4],
    uint32_t a0, uint32_t a1, uint32_t a2, uint32_t a3,
    uint32_t b0, uint32_t b1)
{
    asm volatile(
        "mma.sync.aligned.m16n8k16.row.col.f32.f16.f16.f32 "
        "{%0,%1,%2,%3}, {%4,%5,%6,%7}, {%8,%9}, {%0,%1,%2,%3};"
        : "+f"(c[0]), "+f"(c[1]), "+f"(c[2]), "+f"(c[3])
        : "r"(a0), "r"(a1), "r"(a2), "r"(a3), "r"(b0), "r"(b1));
}

__device__ __forceinline__ void cp16(void* dst_smem, const void* src) {
    uint32_t d = (uint32_t)__cvta_generic_to_shared(dst_smem);
    asm volatile("cp.async.cg.shared.global [%0], [%1], 16;" :: "r"(d), "l"(src));
}
__device__ __forceinline__ void stg_cs32(__half* p, uint32_t v) {
    asm volatile("st.global.cs.u32 [%0], %1;" :: "l"(p), "r"(v) : "memory");
}
#define CP_COMMIT()  asm volatile("cp.async.commit_group;" ::: "memory")
#define CP_WAIT0()   asm volatile("cp.async.wait_group 0;" ::: "memory")

// ---- prep: K fp32 -> fp16 natural ----
__global__ __launch_bounds__(256)
void prep_k(const float* __restrict__ K)
{
    size_t i = ((size_t)blockIdx.x * 256 + threadIdx.x) * 4;
    float4 v = *(const float4*)(K + i);
    __half2* o = (__half2*)(g_Kh + i);
    o[0] = __floats2half2_rn(v.x, v.y);
    o[1] = __floats2half2_rn(v.z, v.w);
}

// ---- prep: V fp32 [s][d] -> fp16 transposed [d][s] ----
__global__ __launch_bounds__(256)
void prep_v(const float* __restrict__ V)
{
    __shared__ float tile[64][65];
    const int bh = blockIdx.y, s0 = blockIdx.x * 64;
    const float* Vb = V + ((size_t)bh * SDIM + s0) * DDIM;
    const int t = threadIdx.x;
#pragma unroll
    for (int j = 0; j < 4; j++) {
        int i = t + 256 * j, r = i >> 4, c4 = i & 15;
        float4 v = *(const float4*)(Vb + (size_t)r * DDIM + c4 * 4);
        tile[r][c4 * 4 + 0] = v.x; tile[r][c4 * 4 + 1] = v.y;
        tile[r][c4 * 4 + 2] = v.z; tile[r][c4 * 4 + 3] = v.w;
    }
    __syncthreads();
    const int d = t >> 2, sb = (t & 3) * 16;
    __half2* o = (__half2*)(g_Vt + ((size_t)bh * DDIM + d) * SDIM + s0 + sb);
#pragma unroll
    for (int k = 0; k < 8; k++)
        o[k] = __floats2half2_rn(tile[sb + 2 * k][d], tile[sb + 2 * k + 1][d]);
}

// =================== k1: scores + exp + W16 + row sums ===================
__global__ __launch_bounds__(THREADS, 2)
void attn_score(const float* __restrict__ Q, const int* __restrict__ M)
{
    extern __shared__ __half smh[];
    __half* Ksm = smh;                          // [2][64 x 88]
    int*    Msm = (int*)(smh + 2 * 64 * KSTRH); // [2][128 x 68]

    const int t    = threadIdx.x;
    const int w    = t >> 5;
    const int lane = t & 31;
    const int grp  = lane >> 2;
    const int tig  = lane & 3;
    const int bh   = blockIdx.y;
    const int qw   = blockIdx.x * TQ + w * WQ;

    const __half* KhB = g_Kh + (size_t)bh * SDIM * DDIM;
    const float*  Qw  = Q + ((size_t)bh * SDIM + qw) * DDIM;
    const int*    McB = M + ((size_t)bh * SDIM + blockIdx.x * TQ) * SDIM;
    __half* Ww = g_W16 + ((size_t)bh * SDIM + qw) * SDIM;

    // chunk-0 loads
#pragma unroll
    for (int j = 0; j < 2; j++) {
        int i = t + THREADS * j, row = i >> 3, seg = i & 7;
        cp16(Ksm + row * KSTRH + seg * 8, KhB + (size_t)row * DDIM + seg * 8);
    }
#pragma unroll
    for (int j = 0; j < 8; j++) {
        int i = t + THREADS * j, row = i >> 4, seg = i & 15;
        cp16(Msm + row * MSTRI + seg * 4, McB + (size_t)row * SDIM + seg * 4);
    }
    CP_COMMIT();

    // Q A-fragments
    uint32_t aq[4][4];
#pragma unroll
    for (int kb = 0; kb < 4; kb++) {
        float2 q00 = *(const float2*)(Qw + (size_t)grp * DDIM + kb * 16 + 2 * tig);
        float2 q10 = *(const float2*)(Qw + (size_t)(grp + 8) * DDIM + kb * 16 + 2 * tig);
        float2 q01 = *(const float2*)(Qw + (size_t)grp * DDIM + kb * 16 + 2 * tig + 8);
        float2 q11 = *(const float2*)(Qw + (size_t)(grp + 8) * DDIM + kb * 16 + 2 * tig + 8);
        aq[kb][0] = f22h(q00.x, q00.y);
        aq[kb][1] = f22h(q10.x, q10.y);
        aq[kb][2] = f22h(q01.x, q01.y);
        aq[kb][3] = f22h(q11.x, q11.y);
    }

    float sum0 = 0.f, sum1 = 0.f;

    for (int c = 0; c < NCH; c++) {
        CP_WAIT0();
        __syncthreads();
        if (c + 1 < NCH) {
            __half* kd = Ksm + ((c + 1) & 1) * (64 * KSTRH);
            int*    md = Msm + ((c + 1) & 1) * (128 * MSTRI);
            const __half* ks = KhB + (size_t)(c + 1) * CK * DDIM;
            const int*    ms = McB + (c + 1) * CK;
#pragma unroll
            for (int j = 0; j < 2; j++) {
                int i = t + THREADS * j, row = i >> 3, seg = i & 7;
                cp16(kd + row * KSTRH + seg * 8, ks + (size_t)row * DDIM + seg * 8);
            }
#pragma unroll
            for (int j = 0; j < 8; j++) {
                int i = t + THREADS * j, row = i >> 4, seg = i & 15;
                cp16(md + row * MSTRI + seg * 4, ms + (size_t)row * SDIM + seg * 4);
            }
            CP_COMMIT();
        }
        const __half* Kc = Ksm + (c & 1) * (64 * KSTRH);
        const int* Mr0 = Msm + (c & 1) * (128 * MSTRI) + (w * 16 + grp) * MSTRI;
        const int* Mr1 = Mr0 + 8 * MSTRI;

#pragma unroll
        for (int s = 0; s < 2; s++) {
            int2 mk0[4], mk1[4];
#pragma unroll
            for (int n2 = 0; n2 < 4; n2++) {
                const int nt = s * 4 + n2;
                mk0[n2] = *(const int2*)(Mr0 + nt * 8 + tig * 2);
                mk1[n2] = *(const int2*)(Mr1 + nt * 8 + tig * 2);
            }

            float sa[4][4];
#pragma unroll
            for (int n2 = 0; n2 < 4; n2++) {
                const int nt = s * 4 + n2;
                float acc[4] = {0.f, 0.f, 0.f, 0.f};
                const __half* kr = Kc + (nt * 8 + grp) * KSTRH + 2 * tig;
#pragma unroll
                for (int kb = 0; kb < 4; kb++) {
                    uint32_t b0 = *(const uint32_t*)(kr + kb * 16);
                    uint32_t b1 = *(const uint32_t*)(kr + kb * 16 + 8);
                    mma_f16(acc, aq[kb][0], aq[kb][1], aq[kb][2], aq[kb][3], b0, b1);
                }
                sa[n2][0] = acc[0]; sa[n2][1] = acc[1];
                sa[n2][2] = acc[2]; sa[n2][3] = acc[3];
            }

#pragma unroll
            for (int n2 = 0; n2 < 4; n2++) {
                const int nt = s * 4 + n2;
                float e00 = mk0[n2].x ? 0.f : __expf(sa[n2][0] * SCALE);
                float e01 = mk0[n2].y ? 0.f : __expf(sa[n2][1] * SCALE);
                float e10 = mk1[n2].x ? 0.f : __expf(sa[n2][2] * SCALE);
                float e11 = mk1[n2].y ? 0.f : __expf(sa[n2][3] * SCALE);
                sum0 += e00 + e01;
                sum1 += e10 + e11;
                stg_cs32(Ww + (size_t)grp * SDIM + c * CK + nt * 8 + tig * 2,
                         f22h(e00, e01));
                stg_cs32(Ww + (size_t)(grp + 8) * SDIM + c * CK + nt * 8 + tig * 2,
                         f22h(e10, e11));
            }
        }
    }

    sum0 += __shfl_xor_sync(0xffffffffu, sum0, 1);
    sum0 += __shfl_xor_sync(0xffffffffu, sum0, 2);
    sum1 += __shfl_xor_sync(0xffffffffu, sum1, 1);
    sum1 += __shfl_xor_sync(0xffffffffu, sum1, 2);
    if (tig == 0) {
        g_ri[(size_t)bh * SDIM + qw + grp]     = 1.0f / sum0;
        g_ri[(size_t)bh * SDIM + qw + grp + 8] = 1.0f / sum1;
    }
}

// ============ k2: context GEMM + weight normalization, one W16 stream ============
__global__ __launch_bounds__(THREADS, 3)
void attn_ctx(float* __restrict__ ctx, float* __restrict__ wout)
{
    extern __shared__ __half smh[];
    __half* Wsm = smh;                           // [2][128 x 72]
    __half* Vsm = smh + 2 * 128 * WSTRH;         // [2][64 x 72]
    float*  sri = (float*)(smh + 2 * 128 * WSTRH + 2 * 64 * VSTRH2);  // [128]

    const int t    = threadIdx.x;
    const int w    = t >> 5;
    const int lane = t & 31;
    const int grp  = lane >> 2;
    const int tig  = lane & 3;
    const int bh   = blockIdx.y;
    const int q0   = blockIdx.x * TQ;
    const int qw   = q0 + w * WQ;

    const __half* WB  = g_W16 + ((size_t)bh * SDIM + q0) * SDIM;
    const __half* VtB = g_Vt  + (size_t)bh * DDIM * SDIM;
    float* Cw = ctx  + ((size_t)bh * SDIM + qw) * DDIM;
    float* Wo = wout + ((size_t)bh * SDIM + q0) * SDIM;

    if (t < 128) sri[t] = g_ri[(size_t)bh * SDIM + q0 + t];

    // chunk-0 loads: W tile 128x64 halfs, V tile 64x64 halfs
#pragma unroll
    for (int j = 0; j < 4; j++) {
        int i = t + THREADS * j, row = i >> 3, seg = i & 7;
        cp16(Wsm + row * WSTRH + seg * 8, WB + (size_t)row * SDIM + seg * 8);
    }
#pragma unroll
    for (int j = 0; j < 2; j++) {
        int i = t + THREADS * j, row = i >> 3, seg = i & 7;
        cp16(Vsm + row * VSTRH2 + seg * 8, VtB + (size_t)row * SDIM + seg * 8);
    }
    CP_COMMIT();

    float cc[8][4];
#pragma unroll
    for (int dt = 0; dt < 8; dt++)
#pragma unroll
        for (int r = 0; r < 4; r++) cc[dt][r] = 0.f;

    __syncthreads();   // sri visible

    for (int c = 0; c < NCH; c++) {
        CP_WAIT0();
        __syncthreads();
        if (c + 1 < NCH) {
            __half* wd = Wsm + ((c + 1) & 1) * (128 * WSTRH);
            __half* vd = Vsm + ((c + 1) & 1) * (64 * VSTRH2);
            const __half* wsrc = WB + (size_t)(c + 1) * CK;
            const __half* vsrc = VtB + (size_t)(c + 1) * CK;
#pragma unroll
            for (int j = 0; j < 4; j++) {
                int i = t + THREADS * j, row = i >> 3, seg = i & 7;
                cp16(wd + row * WSTRH + seg * 8, wsrc + (size_t)row * SDIM + seg * 8);
            }
#pragma unroll
            for (int j = 0; j < 2; j++) {
                int i = t + THREADS * j, row = i >> 3, seg = i & 7;
                cp16(vd + row * VSTRH2 + seg * 8, vsrc + (size_t)row * SDIM + seg * 8);
            }
            CP_COMMIT();
        }
        const __half* Wc = Wsm + (c & 1) * (128 * WSTRH);
        const __half* Vc = Vsm + (c & 1) * (64 * VSTRH2);

        // ---- context mma: 4 k16-groups x 8 d-tiles ----
#pragma unroll
        for (int g = 0; g < 4; g++) {
            const __half* ar0 = Wc + (w * 16 + grp) * WSTRH + g * 16 + 2 * tig;
            const __half* ar1 = ar0 + 8 * WSTRH;
            uint32_t a0 = *(const uint32_t*)(ar0);
            uint32_t a1 = *(const uint32_t*)(ar1);
            uint32_t a2 = *(const uint32_t*)(ar0 + 8);
            uint32_t a3 = *(const uint32_t*)(ar1 + 8);
#pragma unroll
            for (int dt = 0; dt < 8; dt++) {
                const __half* vr = Vc + (dt * 8 + grp) * VSTRH2 + g * 16 + 2 * tig;
                uint32_t b0 = *(const uint32_t*)(vr);
                uint32_t b1 = *(const uint32_t*)(vr + 8);
                mma_f16(cc[dt], a0, a1, a2, a3, b0, b1);
            }
        }

        // ---- normalize this W tile -> fp32 weights out ----
#pragma unroll
        for (int j = 0; j < 8; j++) {
            int idx = t + j * THREADS;          // 0..2047 float4s
            int row = idx >> 4, c4 = idx & 15;
            float ri = sri[row];
            uint2 hv = *(const uint2*)(Wc + row * WSTRH + c4 * 4);
            float2 f0 = __half22float2(*(const __half2*)&hv.x);
            float2 f1 = __half22float2(*(const __half2*)&hv.y);
            *(float4*)(Wo + (size_t)row * SDIM + c * CK + c4 * 4) =
                make_float4(f0.x * ri, f0.y * ri, f1.x * ri, f1.y * ri);
        }
    }

    // ---- context out ----
    const float ri0 = sri[w * WQ + grp];
    const float ri1 = sri[w * WQ + grp + 8];
#pragma unroll
    for (int dt = 0; dt < 8; dt++) {
        *(float2*)(Cw + (size_t)grp * DDIM + dt * 8 + tig * 2) =
            make_float2(cc[dt][0] * ri0, cc[dt][1] * ri0);
        *(float2*)(Cw + (size_t)(grp + 8) * DDIM + dt * 8 + tig * 2) =
            make_float2(cc[dt][2] * ri1, cc[dt][3] * ri1);
    }
}

extern "C" void kernel_launch(void* const* d_in, const int* in_sizes, int n_in,
                              void* d_out, int out_size)
{
    const float* Q = (const float*)d_in[0];
    const float* K = (const float*)d_in[1];
    const float* V = (const float*)d_in[2];
    const int*   M = (const int*)d_in[3];

    float* ctx  = (float*)d_out;
    float* wout = (float*)d_out + (size_t)BHN * SDIM * DDIM;

    prep_k<<<(BHN * SDIM * DDIM) / (256 * 4), 256>>>(K);
    prep_v<<<dim3(SDIM / 64, BHN), 256>>>(V);

    cudaFuncSetAttribute(attn_score,
                         cudaFuncAttributeMaxDynamicSharedMemorySize, SMEM1_BYTES);
    cudaFuncSetAttribute(attn_ctx,
                         cudaFuncAttributeMaxDynamicSharedMemorySize, SMEM2_BYTES);

    dim3 grid(SDIM / TQ, BHN);
    attn_score<<<grid, THREADS, SMEM1_BYTES>>>(Q, M);
    attn_ctx<<<grid, THREADS, SMEM2_BYTES>>>(ctx, wout);
}